// round 14
// baseline (speedup 1.0000x reference)
#include <cuda_runtime.h>
#include <cstdint>
#include <cstddef>

// Problem constants (fixed by the reference):
//   B=8, C=64, N=2000, T=12, E=64000, HID=32
// Algebra: out[b,e,c] = A[b,idx[e],c] + Bm[b,idy[e],c] + conv_b[c]
//   A  = s1 * (u @ W3) @ CW_L^T + conv_b,   u[b,n,c] = sum_t x[b,c,n,t] * (t/11)
//   Bm = s2 * (v @ W4) @ CW_R^T,            v[b,n,c] = sum_t x[b,c,n,t] * (1-t/11)

namespace {
constexpr int Bc = 8;
constexpr int Cc = 64;
constexpr int Nc = 2000;
constexpr int Tc = 12;
constexpr int Ec = 64000;
constexpr int Hc = 32;
constexpr int TILE_N = 64;
constexpr int EDGES_PER_CTA = 256;

// node_kernel shared layout (floats), total 16384 floats = 64 KB.
// ZU/ZV OVERLAY the U region (U/V are dead after phase 2a's reads; a barrier
// separates the last U/V read from the first ZU/ZV write). 64 KB -> 3 CTAs/SM
// (vs 80 KB -> 2), so all 256 CTAs fit in ONE wave (148*3 = 444 slots).
constexpr int SM_U   = 0;      // u_s [c][nl]  64x64   (phase 1/2a)
constexpr int SM_V   = 4096;   // v_s [c][nl]  64x64   (phase 1/2a)
constexpr int SM_ZU  = 0;      // z_u [h][nl]  32x64   (phase 2a out / 2b in)
constexpr int SM_ZV  = 2048;   // z_v [h][nl]  32x64
constexpr int SM_W3  = 8192;   // w3  [c][h]   64x32
constexpr int SM_W4  = 10240;  // w4  [c][h]   64x32
constexpr int SM_CWL = 12288;  // cwL [h][co]  32x64  (transposed conv_w left)
constexpr int SM_CWR = 14336;  // cwR [h][co]  32x64  (transposed conv_w right)
constexpr int SM_TOTAL_BYTES = 16384 * 4;
}

// Device scratch (no allocation allowed in kernel_launch).
__device__ float g_A[(size_t)Bc * Nc * Cc];   // 4 MB
__device__ float g_Bm[(size_t)Bc * Nc * Cc];  // 4 MB

// ---------------------------------------------------------------------------
// Node kernel: builds per-node tables A/Bm. One CTA = (b, 64-node tile),
// 256 threads, grid 32 x 8, single wave at 3 CTAs/SM.
// ---------------------------------------------------------------------------
__global__ void __launch_bounds__(256) node_kernel(const float* __restrict__ x,
                                                   const float* __restrict__ W3,
                                                   const float* __restrict__ W4,
                                                   const float* __restrict__ conv_w,
                                                   const float* __restrict__ conv_b,
                                                   const float* __restrict__ w1s,
                                                   const float* __restrict__ w2s) {
    extern __shared__ float sm[];
    const int tid = threadIdx.x;
    const int b   = blockIdx.y;
    const int n0  = blockIdx.x * TILE_N;

    // ---- Stage weight LDGs EARLY (latency hidden under phase-1 x reads) ----
    float4 w3r[2], w4r[2], cwr[4];
#pragma unroll
    for (int k = 0; k < 2; ++k) {
        w3r[k] = reinterpret_cast<const float4*>(W3)[tid + k * 256];
        w4r[k] = reinterpret_cast<const float4*>(W4)[tid + k * 256];
    }
#pragma unroll
    for (int k = 0; k < 4; ++k)
        cwr[k] = reinterpret_cast<const float4*>(conv_w)[tid + k * 256];
    const float s1 = __ldg(w1s);
    const float s2 = __ldg(w2s);

    // ---- Phase 1: time reduction into u_s/v_s ([c][nl], conflict-free) ----
    const int n_local = tid & 63;
    const int c0      = tid >> 6;    // 0..3
    const int n       = n0 + n_local;
#pragma unroll
    for (int c = c0; c < Cc; c += 4) {
        float u = 0.f, v = 0.f;
        if (n < Nc) {
            const float4* xp = reinterpret_cast<const float4*>(
                x + ((size_t)(b * Cc + c) * Nc + n) * Tc);
            const float4 a0 = xp[0];
            const float4 a1 = xp[1];
            const float4 a2 = xp[2];
            const float xv[12] = {a0.x, a0.y, a0.z, a0.w,
                                  a1.x, a1.y, a1.z, a1.w,
                                  a2.x, a2.y, a2.z, a2.w};
#pragma unroll
            for (int t = 0; t < Tc; ++t) {
                const float tu = (float)t * (1.0f / 11.0f);
                u = fmaf(xv[t], tu, u);
                v = fmaf(xv[t], 1.0f - tu, v);
            }
        }
        sm[SM_U + c * 64 + n_local] = u;
        sm[SM_V + c * 64 + n_local] = v;
    }

    // ---- Commit staged weights to shared ----
#pragma unroll
    for (int k = 0; k < 2; ++k) {
        reinterpret_cast<float4*>(sm + SM_W3)[tid + k * 256] = w3r[k];
        reinterpret_cast<float4*>(sm + SM_W4)[tid + k * 256] = w4r[k];
    }
#pragma unroll
    for (int k = 0; k < 4; ++k) {
        const int f   = tid + k * 256;      // float4 index into conv_w [co][64]
        const int co  = f >> 4;             // 16 float4 per row
        const int hh4 = (f & 15) * 4;       // 0..60
        const float cv[4] = {cwr[k].x, cwr[k].y, cwr[k].z, cwr[k].w};
#pragma unroll
        for (int j = 0; j < 4; ++j) {
            const int hh = hh4 + j;
            if (hh < Hc) sm[SM_CWL + hh * 64 + co]        = cv[j];
            else         sm[SM_CWR + (hh - Hc) * 64 + co] = cv[j];
        }
    }
    __syncthreads();

    // ---- Phase 2a: z_u = u @ W3, z_v = v @ W4  (64n x 32h per tile) ----
    // Accumulate fully into registers, THEN barrier, THEN store into the
    // (now dead) U region. This overlay is what gets smem to 64 KB.
    {
        const int n4 = (tid & 15) * 4;
        const int h2 = (tid >> 4) * 2;
        float au0x=0,au0y=0,au0z=0,au0w=0, au1x=0,au1y=0,au1z=0,au1w=0;
        float av0x=0,av0y=0,av0z=0,av0w=0, av1x=0,av1y=0,av1z=0,av1w=0;
#pragma unroll
        for (int c = 0; c < Cc; ++c) {
            const float4 u4 = *reinterpret_cast<const float4*>(sm + SM_U + c * 64 + n4);
            const float4 v4 = *reinterpret_cast<const float4*>(sm + SM_V + c * 64 + n4);
            const float w3a = sm[SM_W3 + c * Hc + h2];
            const float w3b = sm[SM_W3 + c * Hc + h2 + 1];
            const float w4a = sm[SM_W4 + c * Hc + h2];
            const float w4b = sm[SM_W4 + c * Hc + h2 + 1];
            au0x = fmaf(u4.x, w3a, au0x); au0y = fmaf(u4.y, w3a, au0y);
            au0z = fmaf(u4.z, w3a, au0z); au0w = fmaf(u4.w, w3a, au0w);
            au1x = fmaf(u4.x, w3b, au1x); au1y = fmaf(u4.y, w3b, au1y);
            au1z = fmaf(u4.z, w3b, au1z); au1w = fmaf(u4.w, w3b, au1w);
            av0x = fmaf(v4.x, w4a, av0x); av0y = fmaf(v4.y, w4a, av0y);
            av0z = fmaf(v4.z, w4a, av0z); av0w = fmaf(v4.w, w4a, av0w);
            av1x = fmaf(v4.x, w4b, av1x); av1y = fmaf(v4.y, w4b, av1y);
            av1z = fmaf(v4.z, w4b, av1z); av1w = fmaf(v4.w, w4b, av1w);
        }
        __syncthreads();   // all U/V reads complete before ZU/ZV overwrite them
        *reinterpret_cast<float4*>(sm + SM_ZU + h2 * 64 + n4)       = make_float4(s1*au0x, s1*au0y, s1*au0z, s1*au0w);
        *reinterpret_cast<float4*>(sm + SM_ZU + (h2 + 1) * 64 + n4) = make_float4(s1*au1x, s1*au1y, s1*au1z, s1*au1w);
        *reinterpret_cast<float4*>(sm + SM_ZV + h2 * 64 + n4)       = make_float4(s2*av0x, s2*av0y, s2*av0z, s2*av0w);
        *reinterpret_cast<float4*>(sm + SM_ZV + (h2 + 1) * 64 + n4) = make_float4(s2*av1x, s2*av1y, s2*av1z, s2*av1w);
    }
    __syncthreads();

    // ---- Phase 2b: A = z_u @ cwL^T (+bias), Bm = z_v @ cwR^T ----
    {
        const int co4 = (tid & 15) * 4;
        const int n4g = (tid >> 4) * 4;
        float accA[4][4] = {};
        float accB[4][4] = {};
#pragma unroll
        for (int h = 0; h < Hc; ++h) {
            const float4 zu = *reinterpret_cast<const float4*>(sm + SM_ZU + h * 64 + n4g);
            const float4 zv = *reinterpret_cast<const float4*>(sm + SM_ZV + h * 64 + n4g);
            const float4 cl = *reinterpret_cast<const float4*>(sm + SM_CWL + h * 64 + co4);
            const float4 cr = *reinterpret_cast<const float4*>(sm + SM_CWR + h * 64 + co4);
            const float zus[4] = {zu.x, zu.y, zu.z, zu.w};
            const float zvs[4] = {zv.x, zv.y, zv.z, zv.w};
            const float cls[4] = {cl.x, cl.y, cl.z, cl.w};
            const float crs[4] = {cr.x, cr.y, cr.z, cr.w};
#pragma unroll
            for (int i = 0; i < 4; ++i)
#pragma unroll
                for (int j = 0; j < 4; ++j) {
                    accA[i][j] = fmaf(zus[i], cls[j], accA[i][j]);
                    accB[i][j] = fmaf(zvs[i], crs[j], accB[i][j]);
                }
        }
        const float4 cb4 = *reinterpret_cast<const float4*>(conv_b + co4);
        const float cbs[4] = {cb4.x, cb4.y, cb4.z, cb4.w};
#pragma unroll
        for (int i = 0; i < 4; ++i) {
            const int nn = n0 + n4g + i;
            if (nn < Nc) {
                float4 oa, ob;
                oa.x = accA[i][0] + cbs[0]; oa.y = accA[i][1] + cbs[1];
                oa.z = accA[i][2] + cbs[2]; oa.w = accA[i][3] + cbs[3];
                ob.x = accB[i][0]; ob.y = accB[i][1];
                ob.z = accB[i][2]; ob.w = accB[i][3];
                reinterpret_cast<float4*>(g_A  + ((size_t)b * Nc + nn) * 64 + co4)[0] = oa;
                reinterpret_cast<float4*>(g_Bm + ((size_t)b * Nc + nn) * 64 + co4)[0] = ob;
            }
        }
    }
}

// ---------------------------------------------------------------------------
// Edge kernel v2 (unchanged, audited): out[b,e,c] = A[b,idx[e],c] + Bm[b,idy[e],c].
// Round-6 ncu: 30.7us, nothing saturated (L1 54%, L2 50%, DRAM 33%, issue 36%)
// -> latency/CTA-churn bound + L2 write pollution. Fixes:
//  - 250x8 CTAs, 256 edges each; idx/idy staged through shared; 16 edges per
//    thread in 4x4 batches -> 8 concurrent LDG.128 gathers per thread.
//  - __stcs streaming stores (write-once out stays out of L2; tables stay in).
// ---------------------------------------------------------------------------
__global__ void __launch_bounds__(256) edge_kernel(const int* __restrict__ idx,
                                                   const int* __restrict__ idy,
                                                   float* __restrict__ out) {
    __shared__ int s_idx[EDGES_PER_CTA];
    __shared__ int s_idy[EDGES_PER_CTA];

    const int tid = threadIdx.x;
    const int b   = blockIdx.y;
    const int e0  = blockIdx.x * EDGES_PER_CTA;

    s_idx[tid] = __ldg(idx + e0 + tid);
    s_idy[tid] = __ldg(idy + e0 + tid);
    __syncthreads();

    const int lane = tid & 15;            // channel quad (16B each)
    const int row  = tid >> 4;            // 0..15
    const float* __restrict__ Ab  = g_A  + (size_t)b * Nc * 64;
    const float* __restrict__ Bb  = g_Bm + (size_t)b * Nc * 64;
    float* __restrict__ ob = out + ((size_t)b * Ec + e0) * 64;

#pragma unroll
    for (int kk = 0; kk < 4; ++kk) {
        float4 av[4], rv[4];
        int el[4];
#pragma unroll
        for (int j = 0; j < 4; ++j) {
            el[j] = (kk * 4 + j) * 16 + row;
            const int n1 = s_idx[el[j]];
            const int n2 = s_idy[el[j]];
            av[j] = reinterpret_cast<const float4*>(Ab + (size_t)n1 * 64)[lane];
            rv[j] = reinterpret_cast<const float4*>(Bb + (size_t)n2 * 64)[lane];
        }
#pragma unroll
        for (int j = 0; j < 4; ++j) {
            float4 o;
            o.x = av[j].x + rv[j].x;
            o.y = av[j].y + rv[j].y;
            o.z = av[j].z + rv[j].z;
            o.w = av[j].w + rv[j].w;
            __stcs(reinterpret_cast<float4*>(ob + (size_t)el[j] * 64) + lane, o);
        }
    }
}

// ---------------------------------------------------------------------------
extern "C" void kernel_launch(void* const* d_in, const int* in_sizes, int n_in,
                              void* d_out, int out_size) {
    const float* x      = (const float*)d_in[0];
    const int*   idx    = (const int*)  d_in[1];
    const int*   idy    = (const int*)  d_in[2];
    const float* w1s    = (const float*)d_in[3];
    const float* w2s    = (const float*)d_in[4];
    const float* W3     = (const float*)d_in[5];
    const float* W4     = (const float*)d_in[6];
    const float* conv_w = (const float*)d_in[7];
    const float* conv_b = (const float*)d_in[8];
    float*       out    = (float*)d_out;

    cudaFuncSetAttribute(node_kernel,
                         cudaFuncAttributeMaxDynamicSharedMemorySize, SM_TOTAL_BYTES);

    dim3 g1((Nc + TILE_N - 1) / TILE_N, Bc);     // 32 x 8 = 256 CTAs, 1 wave @ 3/SM
    node_kernel<<<g1, 256, SM_TOTAL_BYTES>>>(x, W3, W4, conv_w, conv_b, w1s, w2s);

    dim3 g2(Ec / EDGES_PER_CTA, Bc);              // 250 x 8 = 2000 CTAs
    edge_kernel<<<g2, 256>>>(idx, idy, out);
}

// round 16
// speedup vs baseline: 1.4433x; 1.4433x over previous
#include <cuda_runtime.h>
#include <cstdint>
#include <cstddef>

// Problem constants (fixed by the reference):
//   B=8, C=64, N=2000, T=12, E=64000, HID=32
// Algebra: out[b,e,c] = A[b,idx[e],c] + Bm[b,idy[e],c] + conv_b[c]
//   A  = s1 * (u @ W3) @ CW_L^T + conv_b,   u[b,n,c] = sum_t x[b,c,n,t] * (t/11)
//   Bm = s2 * (v @ W4) @ CW_R^T,            v[b,n,c] = sum_t x[b,c,n,t] * (1-t/11)
//
// ROUND-14 LESSON: deep per-thread gather batching (MLP 8, 2000 fat CTAs)
// REGRESSED the edge kernel 30.7 -> 42.2us (L1tex wavefront-queue overflow:
// issue 36->17%, L1 54->64.5%). The 32000-tiny-CTA shallow-queue regime is
// the right one. This round: exact round-6 structure + ONE change (__stcs).

namespace {
constexpr int Bc = 8;
constexpr int Cc = 64;
constexpr int Nc = 2000;
constexpr int Tc = 12;
constexpr int Ec = 64000;
constexpr int Hc = 32;
constexpr int TILE_N = 64;

// node_kernel shared layout (floats), total 20480 floats = 80 KB (round-6).
constexpr int SM_U   = 0;      // u_s [c][nl]  64x64
constexpr int SM_V   = 4096;   // v_s [c][nl]  64x64
constexpr int SM_ZU  = 8192;   // z_u [h][nl]  32x64
constexpr int SM_ZV  = 10240;  // z_v [h][nl]  32x64
constexpr int SM_W3  = 12288;  // w3  [c][h]   64x32
constexpr int SM_W4  = 14336;  // w4  [c][h]   64x32
constexpr int SM_CWL = 16384;  // cwL [h][co]  32x64  (transposed conv_w left)
constexpr int SM_CWR = 18432;  // cwR [h][co]  32x64  (transposed conv_w right)
constexpr int SM_TOTAL_BYTES = 20480 * 4;
}

// Device scratch (no allocation allowed in kernel_launch).
__device__ float g_A[(size_t)Bc * Nc * Cc];   // 4 MB
__device__ float g_Bm[(size_t)Bc * Nc * Cc];  // 4 MB

// ---------------------------------------------------------------------------
// Node kernel: builds per-node tables A/Bm. One CTA = (b, 64-node tile),
// 256 threads, grid 32 x 8. EXACT round-6 version (known 57.5us total).
// ---------------------------------------------------------------------------
__global__ void __launch_bounds__(256) node_kernel(const float* __restrict__ x,
                                                   const float* __restrict__ W3,
                                                   const float* __restrict__ W4,
                                                   const float* __restrict__ conv_w,
                                                   const float* __restrict__ conv_b,
                                                   const float* __restrict__ w1s,
                                                   const float* __restrict__ w2s) {
    extern __shared__ float sm[];
    const int tid = threadIdx.x;
    const int b   = blockIdx.y;
    const int n0  = blockIdx.x * TILE_N;

    // ---- Stage weight LDGs EARLY (latency hidden under phase-1 x reads) ----
    float4 w3r[2], w4r[2], cwr[4];
#pragma unroll
    for (int k = 0; k < 2; ++k) {
        w3r[k] = reinterpret_cast<const float4*>(W3)[tid + k * 256];
        w4r[k] = reinterpret_cast<const float4*>(W4)[tid + k * 256];
    }
#pragma unroll
    for (int k = 0; k < 4; ++k)
        cwr[k] = reinterpret_cast<const float4*>(conv_w)[tid + k * 256];
    const float s1 = __ldg(w1s);
    const float s2 = __ldg(w2s);

    // ---- Phase 1: time reduction into u_s/v_s ([c][nl], conflict-free) ----
    const int n_local = tid & 63;
    const int c0      = tid >> 6;    // 0..3
    const int n       = n0 + n_local;
#pragma unroll
    for (int c = c0; c < Cc; c += 4) {
        float u = 0.f, v = 0.f;
        if (n < Nc) {
            const float4* xp = reinterpret_cast<const float4*>(
                x + ((size_t)(b * Cc + c) * Nc + n) * Tc);
            const float4 a0 = xp[0];
            const float4 a1 = xp[1];
            const float4 a2 = xp[2];
            const float xv[12] = {a0.x, a0.y, a0.z, a0.w,
                                  a1.x, a1.y, a1.z, a1.w,
                                  a2.x, a2.y, a2.z, a2.w};
#pragma unroll
            for (int t = 0; t < Tc; ++t) {
                const float tu = (float)t * (1.0f / 11.0f);
                u = fmaf(xv[t], tu, u);
                v = fmaf(xv[t], 1.0f - tu, v);
            }
        }
        sm[SM_U + c * 64 + n_local] = u;
        sm[SM_V + c * 64 + n_local] = v;
    }

    // ---- Commit staged weights to shared ----
#pragma unroll
    for (int k = 0; k < 2; ++k) {
        reinterpret_cast<float4*>(sm + SM_W3)[tid + k * 256] = w3r[k];
        reinterpret_cast<float4*>(sm + SM_W4)[tid + k * 256] = w4r[k];
    }
#pragma unroll
    for (int k = 0; k < 4; ++k) {
        const int f   = tid + k * 256;      // float4 index into conv_w [co][64]
        const int co  = f >> 4;             // 16 float4 per row
        const int hh4 = (f & 15) * 4;       // 0..60
        const float cv[4] = {cwr[k].x, cwr[k].y, cwr[k].z, cwr[k].w};
#pragma unroll
        for (int j = 0; j < 4; ++j) {
            const int hh = hh4 + j;
            if (hh < Hc) sm[SM_CWL + hh * 64 + co]        = cv[j];
            else         sm[SM_CWR + (hh - Hc) * 64 + co] = cv[j];
        }
    }
    __syncthreads();

    // ---- Phase 2a: z_u = u @ W3, z_v = v @ W4  (64n x 32h per tile) ----
    {
        const int n4 = (tid & 15) * 4;
        const int h2 = (tid >> 4) * 2;
        float au0x=0,au0y=0,au0z=0,au0w=0, au1x=0,au1y=0,au1z=0,au1w=0;
        float av0x=0,av0y=0,av0z=0,av0w=0, av1x=0,av1y=0,av1z=0,av1w=0;
#pragma unroll
        for (int c = 0; c < Cc; ++c) {
            const float4 u4 = *reinterpret_cast<const float4*>(sm + SM_U + c * 64 + n4);
            const float4 v4 = *reinterpret_cast<const float4*>(sm + SM_V + c * 64 + n4);
            const float w3a = sm[SM_W3 + c * Hc + h2];
            const float w3b = sm[SM_W3 + c * Hc + h2 + 1];
            const float w4a = sm[SM_W4 + c * Hc + h2];
            const float w4b = sm[SM_W4 + c * Hc + h2 + 1];
            au0x = fmaf(u4.x, w3a, au0x); au0y = fmaf(u4.y, w3a, au0y);
            au0z = fmaf(u4.z, w3a, au0z); au0w = fmaf(u4.w, w3a, au0w);
            au1x = fmaf(u4.x, w3b, au1x); au1y = fmaf(u4.y, w3b, au1y);
            au1z = fmaf(u4.z, w3b, au1z); au1w = fmaf(u4.w, w3b, au1w);
            av0x = fmaf(v4.x, w4a, av0x); av0y = fmaf(v4.y, w4a, av0y);
            av0z = fmaf(v4.z, w4a, av0z); av0w = fmaf(v4.w, w4a, av0w);
            av1x = fmaf(v4.x, w4b, av1x); av1y = fmaf(v4.y, w4b, av1y);
            av1z = fmaf(v4.z, w4b, av1z); av1w = fmaf(v4.w, w4b, av1w);
        }
        *reinterpret_cast<float4*>(sm + SM_ZU + h2 * 64 + n4)       = make_float4(s1*au0x, s1*au0y, s1*au0z, s1*au0w);
        *reinterpret_cast<float4*>(sm + SM_ZU + (h2 + 1) * 64 + n4) = make_float4(s1*au1x, s1*au1y, s1*au1z, s1*au1w);
        *reinterpret_cast<float4*>(sm + SM_ZV + h2 * 64 + n4)       = make_float4(s2*av0x, s2*av0y, s2*av0z, s2*av0w);
        *reinterpret_cast<float4*>(sm + SM_ZV + (h2 + 1) * 64 + n4) = make_float4(s2*av1x, s2*av1y, s2*av1z, s2*av1w);
    }
    __syncthreads();

    // ---- Phase 2b: A = z_u @ cwL^T (+bias), Bm = z_v @ cwR^T ----
    {
        const int co4 = (tid & 15) * 4;
        const int n4g = (tid >> 4) * 4;
        float accA[4][4] = {};
        float accB[4][4] = {};
#pragma unroll
        for (int h = 0; h < Hc; ++h) {
            const float4 zu = *reinterpret_cast<const float4*>(sm + SM_ZU + h * 64 + n4g);
            const float4 zv = *reinterpret_cast<const float4*>(sm + SM_ZV + h * 64 + n4g);
            const float4 cl = *reinterpret_cast<const float4*>(sm + SM_CWL + h * 64 + co4);
            const float4 cr = *reinterpret_cast<const float4*>(sm + SM_CWR + h * 64 + co4);
            const float zus[4] = {zu.x, zu.y, zu.z, zu.w};
            const float zvs[4] = {zv.x, zv.y, zv.z, zv.w};
            const float cls[4] = {cl.x, cl.y, cl.z, cl.w};
            const float crs[4] = {cr.x, cr.y, cr.z, cr.w};
#pragma unroll
            for (int i = 0; i < 4; ++i)
#pragma unroll
                for (int j = 0; j < 4; ++j) {
                    accA[i][j] = fmaf(zus[i], cls[j], accA[i][j]);
                    accB[i][j] = fmaf(zvs[i], crs[j], accB[i][j]);
                }
        }
        const float4 cb4 = *reinterpret_cast<const float4*>(conv_b + co4);
        const float cbs[4] = {cb4.x, cb4.y, cb4.z, cb4.w};
#pragma unroll
        for (int i = 0; i < 4; ++i) {
            const int nn = n0 + n4g + i;
            if (nn < Nc) {
                float4 oa, ob;
                oa.x = accA[i][0] + cbs[0]; oa.y = accA[i][1] + cbs[1];
                oa.z = accA[i][2] + cbs[2]; oa.w = accA[i][3] + cbs[3];
                ob.x = accB[i][0]; ob.y = accB[i][1];
                ob.z = accB[i][2]; ob.w = accB[i][3];
                reinterpret_cast<float4*>(g_A  + ((size_t)b * Nc + nn) * 64 + co4)[0] = oa;
                reinterpret_cast<float4*>(g_Bm + ((size_t)b * Nc + nn) * 64 + co4)[0] = ob;
            }
        }
    }
}

// ---------------------------------------------------------------------------
// Edge kernel: EXACT round-6 v1 structure (known 30.7us) with ONE change:
// __stcs on the output store. out is written once and never read, but default
// stores write-allocate in L2 and evict the 8MB gather tables (round-6 ncu
// showed DRAM=33% = table re-reads). Streaming stores keep tables L2-resident.
// ---------------------------------------------------------------------------
__global__ void __launch_bounds__(256) edge_kernel(const int* __restrict__ idx,
                                                   const int* __restrict__ idy,
                                                   float* __restrict__ out) {
    const int tid  = threadIdx.x;
    const int lane = tid & 15;
    const int row  = tid >> 4;            // 0..15
    const int e    = blockIdx.x * 16 + row;
    const int b    = blockIdx.y;

    const int n1 = __ldg(idx + e);
    const int n2 = __ldg(idy + e);

    const float4 a = reinterpret_cast<const float4*>(g_A  + ((size_t)b * Nc + n1) * 64)[lane];
    const float4 r = reinterpret_cast<const float4*>(g_Bm + ((size_t)b * Nc + n2) * 64)[lane];

    float4 o;
    o.x = a.x + r.x;
    o.y = a.y + r.y;
    o.z = a.z + r.z;
    o.w = a.w + r.w;

    __stcs(reinterpret_cast<float4*>(out + ((size_t)b * Ec + e) * 64) + lane, o);
}

// ---------------------------------------------------------------------------
extern "C" void kernel_launch(void* const* d_in, const int* in_sizes, int n_in,
                              void* d_out, int out_size) {
    const float* x      = (const float*)d_in[0];
    const int*   idx    = (const int*)  d_in[1];
    const int*   idy    = (const int*)  d_in[2];
    const float* w1s    = (const float*)d_in[3];
    const float* w2s    = (const float*)d_in[4];
    const float* W3     = (const float*)d_in[5];
    const float* W4     = (const float*)d_in[6];
    const float* conv_w = (const float*)d_in[7];
    const float* conv_b = (const float*)d_in[8];
    float*       out    = (float*)d_out;

    cudaFuncSetAttribute(node_kernel,
                         cudaFuncAttributeMaxDynamicSharedMemorySize, SM_TOTAL_BYTES);

    dim3 g1((Nc + TILE_N - 1) / TILE_N, Bc);     // 32 x 8 = 256 CTAs
    node_kernel<<<g1, 256, SM_TOTAL_BYTES>>>(x, W3, W4, conv_w, conv_b, w1s, w2s);

    dim3 g2(Ec / 16, Bc);                         // 4000 x 8 = 32000 CTAs (round-6 regime)
    edge_kernel<<<g2, 256>>>(idx, idy, out);
}

// round 17
// speedup vs baseline: 1.4478x; 1.0031x over previous
#include <cuda_runtime.h>
#include <cstdint>
#include <cstddef>

// Problem constants (fixed by the reference):
//   B=8, C=64, N=2000, T=12, E=64000, HID=32
// Algebra: out[b,e,c] = A[b,idx[e],c] + Bm[b,idy[e],c] + conv_b[c]
//   A  = s1 * (u @ W3) @ CW_L^T + conv_b,   u[b,n,c] = sum_t x[b,c,n,t] * (t/11)
//   Bm = s2 * (v @ W4) @ CW_R^T,            v[b,n,c] = sum_t x[b,c,n,t] * (1-t/11)
//
// History: R6 57.5us baseline. R14: fat-CTA edge (MLP 8) REGRESSED edge
// 30.7->42.2 (L1tex queue overflow). R16: __stcs on edge out -> 51.4us; edge
// profile unchanged (30.7us, at structural floor) but NODE sped up ~6us
// (out no longer leaves L2 dirty for the next replay's node kernel).
// This round: node phase 2 is FMA-bound (~2048 FFMA/thread). Use packed
// fma.rn.f32x2 (sm_103a FFMA2, PTX-only) -> phase-2 FMA issue halves.

namespace {
constexpr int Bc = 8;
constexpr int Cc = 64;
constexpr int Nc = 2000;
constexpr int Tc = 12;
constexpr int Ec = 64000;
constexpr int Hc = 32;
constexpr int TILE_N = 64;

// node_kernel shared layout (floats), total 20480 floats = 80 KB (round-6).
constexpr int SM_U   = 0;      // u_s [c][nl]  64x64
constexpr int SM_V   = 4096;   // v_s [c][nl]  64x64
constexpr int SM_ZU  = 8192;   // z_u [h][nl]  32x64
constexpr int SM_ZV  = 10240;  // z_v [h][nl]  32x64
constexpr int SM_W3  = 12288;  // w3  [c][h]   64x32
constexpr int SM_W4  = 14336;  // w4  [c][h]   64x32
constexpr int SM_CWL = 16384;  // cwL [h][co]  32x64  (transposed conv_w left)
constexpr int SM_CWR = 18432;  // cwR [h][co]  32x64  (transposed conv_w right)
constexpr int SM_TOTAL_BYTES = 20480 * 4;
}

// Device scratch (no allocation allowed in kernel_launch).
__device__ float g_A[(size_t)Bc * Nc * Cc];   // 4 MB
__device__ float g_Bm[(size_t)Bc * Nc * Cc];  // 4 MB

// ---- packed fp32x2 helpers (B300 FFMA2 path; ptxas never auto-fuses) ----
__device__ __forceinline__ void fma2(unsigned long long& d,
                                     unsigned long long a,
                                     unsigned long long b) {
    asm("fma.rn.f32x2 %0, %1, %2, %0;" : "+l"(d) : "l"(a), "l"(b));
}
__device__ __forceinline__ unsigned long long pack2(float x) {
    unsigned long long d;
    asm("mov.b64 %0, {%1, %1};" : "=l"(d) : "f"(x));
    return d;
}
__device__ __forceinline__ void unpack2(float& lo, float& hi, unsigned long long d) {
    asm("mov.b64 {%0, %1}, %2;" : "=f"(lo), "=f"(hi) : "l"(d));
}
__device__ __forceinline__ unsigned long long mul2(unsigned long long a,
                                                   unsigned long long b) {
    unsigned long long d;
    asm("mul.rn.f32x2 %0, %1, %2;" : "=l"(d) : "l"(a), "l"(b));
    return d;
}

// ---------------------------------------------------------------------------
// Node kernel: builds per-node tables A/Bm. One CTA = (b, 64-node tile),
// 256 threads, grid 32 x 8. Phase 1 unchanged from R6; phases 2a/2b use
// f32x2 packed FMA (pairs packed along n — free via ulonglong2 smem loads).
// ---------------------------------------------------------------------------
__global__ void __launch_bounds__(256) node_kernel(const float* __restrict__ x,
                                                   const float* __restrict__ W3,
                                                   const float* __restrict__ W4,
                                                   const float* __restrict__ conv_w,
                                                   const float* __restrict__ conv_b,
                                                   const float* __restrict__ w1s,
                                                   const float* __restrict__ w2s) {
    extern __shared__ float sm[];
    const int tid = threadIdx.x;
    const int b   = blockIdx.y;
    const int n0  = blockIdx.x * TILE_N;

    // ---- Stage weight LDGs EARLY (latency hidden under phase-1 x reads) ----
    float4 w3r[2], w4r[2], cwr[4];
#pragma unroll
    for (int k = 0; k < 2; ++k) {
        w3r[k] = reinterpret_cast<const float4*>(W3)[tid + k * 256];
        w4r[k] = reinterpret_cast<const float4*>(W4)[tid + k * 256];
    }
#pragma unroll
    for (int k = 0; k < 4; ++k)
        cwr[k] = reinterpret_cast<const float4*>(conv_w)[tid + k * 256];
    const float s1 = __ldg(w1s);
    const float s2 = __ldg(w2s);

    // ---- Phase 1: time reduction into u_s/v_s ([c][nl], conflict-free) ----
    const int n_local = tid & 63;
    const int c0      = tid >> 6;    // 0..3
    const int n       = n0 + n_local;
#pragma unroll
    for (int c = c0; c < Cc; c += 4) {
        float u = 0.f, v = 0.f;
        if (n < Nc) {
            const float4* xp = reinterpret_cast<const float4*>(
                x + ((size_t)(b * Cc + c) * Nc + n) * Tc);
            const float4 a0 = xp[0];
            const float4 a1 = xp[1];
            const float4 a2 = xp[2];
            const float xv[12] = {a0.x, a0.y, a0.z, a0.w,
                                  a1.x, a1.y, a1.z, a1.w,
                                  a2.x, a2.y, a2.z, a2.w};
#pragma unroll
            for (int t = 0; t < Tc; ++t) {
                const float tu = (float)t * (1.0f / 11.0f);
                u = fmaf(xv[t], tu, u);
                v = fmaf(xv[t], 1.0f - tu, v);
            }
        }
        sm[SM_U + c * 64 + n_local] = u;
        sm[SM_V + c * 64 + n_local] = v;
    }

    // ---- Commit staged weights to shared ----
#pragma unroll
    for (int k = 0; k < 2; ++k) {
        reinterpret_cast<float4*>(sm + SM_W3)[tid + k * 256] = w3r[k];
        reinterpret_cast<float4*>(sm + SM_W4)[tid + k * 256] = w4r[k];
    }
#pragma unroll
    for (int k = 0; k < 4; ++k) {
        const int f   = tid + k * 256;      // float4 index into conv_w [co][64]
        const int co  = f >> 4;             // 16 float4 per row
        const int hh4 = (f & 15) * 4;       // 0..60
        const float cv[4] = {cwr[k].x, cwr[k].y, cwr[k].z, cwr[k].w};
#pragma unroll
        for (int j = 0; j < 4; ++j) {
            const int hh = hh4 + j;
            if (hh < Hc) sm[SM_CWL + hh * 64 + co]        = cv[j];
            else         sm[SM_CWR + (hh - Hc) * 64 + co] = cv[j];
        }
    }
    __syncthreads();

    // ---- Phase 2a: z_u = u @ W3, z_v = v @ W4  (f32x2, pairs along n) ----
    // Thread tile: 4 n (2 pairs) x 2 h. 8 FFMA2 per c (was 16 FFMA).
    {
        const int n4 = (tid & 15) * 4;
        const int h2 = (tid >> 4) * 2;
        unsigned long long aU[4] = {0ull, 0ull, 0ull, 0ull};  // [h][npair]
        unsigned long long aV[4] = {0ull, 0ull, 0ull, 0ull};
#pragma unroll
        for (int c = 0; c < Cc; ++c) {
            const ulonglong2 u2 = *reinterpret_cast<const ulonglong2*>(sm + SM_U + c * 64 + n4);
            const ulonglong2 v2 = *reinterpret_cast<const ulonglong2*>(sm + SM_V + c * 64 + n4);
            const unsigned long long w3a2 = pack2(sm[SM_W3 + c * Hc + h2]);
            const unsigned long long w3b2 = pack2(sm[SM_W3 + c * Hc + h2 + 1]);
            const unsigned long long w4a2 = pack2(sm[SM_W4 + c * Hc + h2]);
            const unsigned long long w4b2 = pack2(sm[SM_W4 + c * Hc + h2 + 1]);
            fma2(aU[0], u2.x, w3a2); fma2(aU[1], u2.y, w3a2);
            fma2(aU[2], u2.x, w3b2); fma2(aU[3], u2.y, w3b2);
            fma2(aV[0], v2.x, w4a2); fma2(aV[1], v2.y, w4a2);
            fma2(aV[2], v2.x, w4b2); fma2(aV[3], v2.y, w4b2);
        }
        const unsigned long long s1p = pack2(s1);
        const unsigned long long s2p = pack2(s2);
        *reinterpret_cast<ulonglong2*>(sm + SM_ZU + h2 * 64 + n4) =
            make_ulonglong2(mul2(aU[0], s1p), mul2(aU[1], s1p));
        *reinterpret_cast<ulonglong2*>(sm + SM_ZU + (h2 + 1) * 64 + n4) =
            make_ulonglong2(mul2(aU[2], s1p), mul2(aU[3], s1p));
        *reinterpret_cast<ulonglong2*>(sm + SM_ZV + h2 * 64 + n4) =
            make_ulonglong2(mul2(aV[0], s2p), mul2(aV[1], s2p));
        *reinterpret_cast<ulonglong2*>(sm + SM_ZV + (h2 + 1) * 64 + n4) =
            make_ulonglong2(mul2(aV[2], s2p), mul2(aV[3], s2p));
    }
    __syncthreads();

    // ---- Phase 2b: A = z_u @ cwL^T (+bias), Bm = z_v @ cwR^T (f32x2) ----
    // Thread tile: 4 n (2 pairs) x 4 co, both matrices. 16 FFMA2 per h (was 32 FFMA).
    {
        const int co4 = (tid & 15) * 4;
        const int n4g = (tid >> 4) * 4;
        unsigned long long accA2[2][4] = {};
        unsigned long long accB2[2][4] = {};
#pragma unroll
        for (int h = 0; h < Hc; ++h) {
            const ulonglong2 zu2 = *reinterpret_cast<const ulonglong2*>(sm + SM_ZU + h * 64 + n4g);
            const ulonglong2 zv2 = *reinterpret_cast<const ulonglong2*>(sm + SM_ZV + h * 64 + n4g);
            const float4 cl = *reinterpret_cast<const float4*>(sm + SM_CWL + h * 64 + co4);
            const float4 cr = *reinterpret_cast<const float4*>(sm + SM_CWR + h * 64 + co4);
            const unsigned long long cl2[4] = {pack2(cl.x), pack2(cl.y), pack2(cl.z), pack2(cl.w)};
            const unsigned long long cr2[4] = {pack2(cr.x), pack2(cr.y), pack2(cr.z), pack2(cr.w)};
#pragma unroll
            for (int j = 0; j < 4; ++j) {
                fma2(accA2[0][j], zu2.x, cl2[j]);
                fma2(accA2[1][j], zu2.y, cl2[j]);
                fma2(accB2[0][j], zv2.x, cr2[j]);
                fma2(accB2[1][j], zv2.y, cr2[j]);
            }
        }
        // Unpack (register-pair aliasing; near-free) then bias + store as before.
        float accA[4][4], accB[4][4];
#pragma unroll
        for (int p = 0; p < 2; ++p)
#pragma unroll
            for (int j = 0; j < 4; ++j) {
                unpack2(accA[2 * p][j], accA[2 * p + 1][j], accA2[p][j]);
                unpack2(accB[2 * p][j], accB[2 * p + 1][j], accB2[p][j]);
            }
        const float4 cb4 = *reinterpret_cast<const float4*>(conv_b + co4);
        const float cbs[4] = {cb4.x, cb4.y, cb4.z, cb4.w};
#pragma unroll
        for (int i = 0; i < 4; ++i) {
            const int nn = n0 + n4g + i;
            if (nn < Nc) {
                float4 oa, ob;
                oa.x = accA[i][0] + cbs[0]; oa.y = accA[i][1] + cbs[1];
                oa.z = accA[i][2] + cbs[2]; oa.w = accA[i][3] + cbs[3];
                ob.x = accB[i][0]; ob.y = accB[i][1];
                ob.z = accB[i][2]; ob.w = accB[i][3];
                reinterpret_cast<float4*>(g_A  + ((size_t)b * Nc + nn) * 64 + co4)[0] = oa;
                reinterpret_cast<float4*>(g_Bm + ((size_t)b * Nc + nn) * 64 + co4)[0] = ob;
            }
        }
    }
}

// ---------------------------------------------------------------------------
// Edge kernel: round-16 version (30.7us, at structural floor — do not touch).
// __stcs keeps the 131MB write-once stream out of L2 so the NEXT replay's
// node kernel starts with a clean cache (the actual R16 win mechanism).
// ---------------------------------------------------------------------------
__global__ void __launch_bounds__(256) edge_kernel(const int* __restrict__ idx,
                                                   const int* __restrict__ idy,
                                                   float* __restrict__ out) {
    const int tid  = threadIdx.x;
    const int lane = tid & 15;
    const int row  = tid >> 4;            // 0..15
    const int e    = blockIdx.x * 16 + row;
    const int b    = blockIdx.y;

    const int n1 = __ldg(idx + e);
    const int n2 = __ldg(idy + e);

    const float4 a = reinterpret_cast<const float4*>(g_A  + ((size_t)b * Nc + n1) * 64)[lane];
    const float4 r = reinterpret_cast<const float4*>(g_Bm + ((size_t)b * Nc + n2) * 64)[lane];

    float4 o;
    o.x = a.x + r.x;
    o.y = a.y + r.y;
    o.z = a.z + r.z;
    o.w = a.w + r.w;

    __stcs(reinterpret_cast<float4*>(out + ((size_t)b * Ec + e) * 64) + lane, o);
}

// ---------------------------------------------------------------------------
extern "C" void kernel_launch(void* const* d_in, const int* in_sizes, int n_in,
                              void* d_out, int out_size) {
    const float* x      = (const float*)d_in[0];
    const int*   idx    = (const int*)  d_in[1];
    const int*   idy    = (const int*)  d_in[2];
    const float* w1s    = (const float*)d_in[3];
    const float* w2s    = (const float*)d_in[4];
    const float* W3     = (const float*)d_in[5];
    const float* W4     = (const float*)d_in[6];
    const float* conv_w = (const float*)d_in[7];
    const float* conv_b = (const float*)d_in[8];
    float*       out    = (float*)d_out;

    cudaFuncSetAttribute(node_kernel,
                         cudaFuncAttributeMaxDynamicSharedMemorySize, SM_TOTAL_BYTES);

    dim3 g1((Nc + TILE_N - 1) / TILE_N, Bc);     // 32 x 8 = 256 CTAs
    node_kernel<<<g1, 256, SM_TOTAL_BYTES>>>(x, W3, W4, conv_w, conv_b, w1s, w2s);

    dim3 g2(Ec / 16, Bc);                         // 4000 x 8 = 32000 CTAs
    edge_kernel<<<g2, 256>>>(idx, idy, out);
}